// round 15
// baseline (speedup 1.0000x reference)
#include <cuda_runtime.h>
#include <cuda_fp16.h>
#include <cstdint>

#define BB 128
#define TT 1024
#define HH 128
#define NG 512
#define EPAD 112
#define MR (TT*BB)   // 131072

// ---------------- scratch (static device globals; no allocs) ----------------
__device__ float g_e[(size_t)MR * EPAD];        // embedded input, K padded to 112
__device__ float g_xp[(size_t)2 * MR * NG];     // gate pre-activations, reused per layer
__device__ float g_h0[(size_t)MR * 256];        // layer0 output [t][b][2H]
__device__ float g_wt0[2 * EPAD * NG];          // w_ih_l0^T padded, per dir
__device__ float g_wt1[2 * 256 * NG];           // w_ih_l1^T, per dir
__device__ __half g_wch[2 * 2 * 32 * NG * 4];   // w_hh fp16 [layer][dir][kc][col][4k]
__device__ float g_bs[2 * 2 * NG];              // b_ih + b_hh
__device__ float g_hf[2 * BB * HH];             // final hidden of layer1 [dir][b][j]

__device__ __forceinline__ float sigf(float x) { return 1.0f / (1.0f + __expf(-x)); }
__device__ __forceinline__ float tanhfast(float x) { return 2.0f / (1.0f + __expf(-2.0f * x)) - 1.0f; }

// packed f32x2 helpers (sm_103a FFMA2 path; see B300_MICROARCH / ptx_helpers)
#define FMA_F32X2(d, a, b, c) \
    asm("fma.rn.f32x2 %0, %1, %2, %3;" : "=l"(d) : "l"(a), "l"(b), "l"(c))
#define PACK2(d, lo, hi) \
    asm("mov.b64 %0, {%1, %2};" : "=l"(d) : "r"(__float_as_uint(lo)), "r"(__float_as_uint(hi)))
#define UNPACK2(lo, hi, s) \
    do { unsigned int _ulo, _uhi; \
         asm("mov.b64 {%0, %1}, %2;" : "=r"(_ulo), "=r"(_uhi) : "l"(s)); \
         lo = __uint_as_float(_ulo); hi = __uint_as_float(_uhi); } while (0)

// ---------------- embedding gather into padded [t][b][112] ----------------
__global__ void k_embed(const int* __restrict__ x, const float* __restrict__ emb) {
    size_t idx = (size_t)blockIdx.x * blockDim.x + threadIdx.x;
    if (idx >= (size_t)MR * EPAD) return;
    int d = (int)(idx % EPAD);
    size_t m = idx / EPAD;
    int b = (int)(m % BB);
    int t = (int)(m / BB);
    float v = 0.0f;
    if (d < 100) {
        int tok = x[b * TT + t];
        v = emb[(size_t)tok * 100 + d];
    }
    g_e[idx] = v;
}

// ---------------- weight prep (z-dim = direction) ----------------
// wt[k][n] = w_ih[n][k], zero-padded in k
__global__ void k_wt(const float* __restrict__ w0, const float* __restrict__ w1,
                     float* __restrict__ wt, int K, int Kpad) {
    int idx = blockIdx.x * blockDim.x + threadIdx.x;
    if (idx >= Kpad * NG) return;
    const float* w = blockIdx.z ? w1 : w0;
    int n = idx % NG;
    int k = idx / NG;
    wt[(size_t)blockIdx.z * Kpad * NG + idx] = (k < K) ? w[n * K + k] : 0.0f;
}

// wch[(kc*512 + col)*4 + i] = fp16(w_hh[col][kc*4+i])
__global__ void k_wch(const float* __restrict__ wh0, const float* __restrict__ wh1,
                      __half* __restrict__ wc) {
    int idx = blockIdx.x * blockDim.x + threadIdx.x;
    if (idx >= 32 * NG * 4) return;
    const float* whh = blockIdx.z ? wh1 : wh0;
    int i = idx & 3;
    int col = (idx >> 2) & (NG - 1);
    int kc = idx >> 11;
    wc[(size_t)blockIdx.z * 32 * NG * 4 + idx] = __float2half(whh[col * HH + kc * 4 + i]);
}

__global__ void k_bias(const float* __restrict__ bi0, const float* __restrict__ bh0,
                       const float* __restrict__ bi1, const float* __restrict__ bh1,
                       float* __restrict__ bs) {
    int idx = blockIdx.x * blockDim.x + threadIdx.x;
    if (idx >= NG) return;
    bs[idx] = bi0[idx] + bh0[idx];
    bs[NG + idx] = bi1[idx] + bh1[idx];
}

// ---------------- fp32 GEMM: C[M,512] = A[M,K] @ Bm[K,512] + bias ----------------
// BM=128, BN=128, BK=16, 256 threads, 8x8 microtile computed as 8x4 f32x2 lanes
// (FFMA2: halves fma-pipe occupancy vs scalar FFMA). Register double buffering.
// gridDim.z = direction: selects Bm/bias/C slice (A shared between dirs).
__global__ __launch_bounds__(256) void k_gemm(const float* __restrict__ A,
                                              const float* __restrict__ Bm_all,
                                              const float* __restrict__ bias_all,
                                              float* __restrict__ Cm_all,
                                              int M, int K) {
    const float* Bm = Bm_all + (size_t)blockIdx.z * K * NG;
    const float* bias = bias_all + (size_t)blockIdx.z * NG;
    float* Cm = Cm_all + (size_t)blockIdx.z * MR * NG;

    __shared__ float As[16][128];
    __shared__ float Bs[16][128];
    int tid = threadIdx.x;
    int tx = tid & 15, ty = tid >> 4;
    int m0 = blockIdx.x * 128;
    int n0 = blockIdx.y * 128;

    unsigned long long acc2[8][4];   // [i][j2]: lo = col 2*j2, hi = col 2*j2+1
#pragma unroll
    for (int i = 0; i < 8; i++)
#pragma unroll
        for (int j = 0; j < 4; j++) acc2[i][j] = 0ull;

    int aRow[2], aKq[2], bRow[2], bC4[2];
#pragma unroll
    for (int q = 0; q < 2; q++) {
        int s = tid + q * 256;
        aRow[q] = s >> 2; aKq[q] = (s & 3) << 2;
        bRow[q] = s >> 5; bC4[q] = (s & 31) << 2;
    }

    float4 va[2], vb[2];
#pragma unroll
    for (int q = 0; q < 2; q++) {
        va[q] = *(const float4*)(A + (size_t)(m0 + aRow[q]) * K + aKq[q]);
        vb[q] = *(const float4*)(Bm + (size_t)bRow[q] * NG + n0 + bC4[q]);
    }

    for (int k0 = 0; k0 < K; k0 += 16) {
#pragma unroll
        for (int q = 0; q < 2; q++) {
            As[aKq[q] + 0][aRow[q]] = va[q].x;
            As[aKq[q] + 1][aRow[q]] = va[q].y;
            As[aKq[q] + 2][aRow[q]] = va[q].z;
            As[aKq[q] + 3][aRow[q]] = va[q].w;
            *(float4*)(&Bs[bRow[q]][bC4[q]]) = vb[q];
        }
        __syncthreads();
        int kn = k0 + 16;
        if (kn < K) {
#pragma unroll
            for (int q = 0; q < 2; q++) {
                va[q] = *(const float4*)(A + (size_t)(m0 + aRow[q]) * K + kn + aKq[q]);
                vb[q] = *(const float4*)(Bm + (size_t)(kn + bRow[q]) * NG + n0 + bC4[q]);
            }
        }
#pragma unroll
        for (int k = 0; k < 16; k++) {
            float ra[8], rb[8];
#pragma unroll
            for (int i = 0; i < 8; i++) ra[i] = As[k][ty * 8 + i];
#pragma unroll
            for (int j = 0; j < 8; j++) rb[j] = Bs[k][tx * 8 + j];
            unsigned long long b2[4];
#pragma unroll
            for (int j = 0; j < 4; j++) PACK2(b2[j], rb[2 * j], rb[2 * j + 1]);
#pragma unroll
            for (int i = 0; i < 8; i++) {
                unsigned long long a2;
                PACK2(a2, ra[i], ra[i]);
#pragma unroll
                for (int j = 0; j < 4; j++)
                    FMA_F32X2(acc2[i][j], a2, b2[j], acc2[i][j]);
            }
        }
        __syncthreads();
    }

    float bv[8];
#pragma unroll
    for (int j = 0; j < 8; j++) bv[j] = bias[n0 + tx * 8 + j];
#pragma unroll
    for (int i = 0; i < 8; i++) {
        int m = m0 + ty * 8 + i;
        float c[8];
#pragma unroll
        for (int j = 0; j < 4; j++) UNPACK2(c[2 * j], c[2 * j + 1], acc2[i][j]);
        float4 o0, o1;
        o0.x = c[0] + bv[0]; o0.y = c[1] + bv[1];
        o0.z = c[2] + bv[2]; o0.w = c[3] + bv[3];
        o1.x = c[4] + bv[4]; o1.y = c[5] + bv[5];
        o1.z = c[6] + bv[6]; o1.w = c[7] + bv[7];
        *(float4*)(Cm + (size_t)m * NG + n0 + tx * 8) = o0;
        *(float4*)(Cm + (size_t)m * NG + n0 + tx * 8 + 4) = o1;
    }
}

// ---------------- recurrent scan (fp16 weights resident in dynamic smem) ----
// grid = 128: dir = bx>>6, batch-tile of 2 rows = bx&63. 512 threads = 1 gate col each.
// Dynamic smem layout:
//   [0      .. 1024)   float h_s[2][128]
//   [1024   .. 7168)   float gb[512*3]   (stride-3 pad: conflict-free)
//   [7168   .. 138240) uint2 w2[32][512] (fp16 w_hh: [kc][col] -> 4 k-values)
#define SCAN_SMEM 138240
__global__ __launch_bounds__(512, 1) void k_scan(const float* __restrict__ xp_all,
                                                 const __half* __restrict__ wch_all,
                                                 float* __restrict__ seq_out,
                                                 float* __restrict__ final_out) {
    extern __shared__ __align__(16) char smem[];
    float* h_s = (float*)smem;                       // [2][128]
    float* gb = (float*)(smem + 1024);               // [512*3]
    uint2* w2 = (uint2*)(smem + 7168);               // [32*512]

    int dir = blockIdx.x >> 6;
    int tile = blockIdx.x & 63;
    int b0 = tile * 2;
    const float* xp = xp_all + (size_t)dir * MR * NG;
    const __half* wch = wch_all + (size_t)dir * (32 * NG * 4);

    int col = threadIdx.x;

    // preload fp16 weights into smem (128 KB), uint4 = 8 halves per load
    {
        const uint4* src = (const uint4*)wch;
        uint4* dst = (uint4*)w2;
#pragma unroll
        for (int i = 0; i < 16; i++) dst[col + (i << 9)] = src[col + (i << 9)];
    }
    if (col < 256) h_s[col] = 0.0f;
    float c0 = 0.0f, c1 = 0.0f;
    __syncthreads();

    for (int s = 0; s < TT; s++) {
        int t = dir ? (TT - 1 - s) : s;
        size_t base = ((size_t)t * BB + b0) * NG + col;
        float x0 = xp[base];
        float x1 = xp[base + NG];
        float s0 = 0.0f, s1 = 0.0f;
#pragma unroll
        for (int kc = 0; kc < 32; kc++) {
            uint2 wv = w2[(kc << 9) + col];
            float2 f01 = __half22float2(*(const __half2*)&wv.x);
            float2 f23 = __half22float2(*(const __half2*)&wv.y);
            float4 ha = *(const float4*)&h_s[kc << 2];
            float4 hb = *(const float4*)&h_s[128 + (kc << 2)];
            s0 += f01.x * ha.x; s0 += f01.y * ha.y; s0 += f23.x * ha.z; s0 += f23.y * ha.w;
            s1 += f01.x * hb.x; s1 += f01.y * hb.y; s1 += f23.x * hb.z; s1 += f23.y * hb.w;
        }
        gb[col * 3 + 0] = x0 + s0;
        gb[col * 3 + 1] = x1 + s1;
        __syncthreads();

        if (col < HH) {
            int j = col;
            float i0 = sigf(gb[j * 3 + 0]);
            float f0 = sigf(gb[(128 + j) * 3 + 0]);
            float g0 = tanhfast(gb[(256 + j) * 3 + 0]);
            float o0 = sigf(gb[(384 + j) * 3 + 0]);
            c0 = f0 * c0 + i0 * g0;
            float h0v = o0 * tanhfast(c0);
            float i1 = sigf(gb[j * 3 + 1]);
            float f1 = sigf(gb[(128 + j) * 3 + 1]);
            float g1 = tanhfast(gb[(256 + j) * 3 + 1]);
            float o1 = sigf(gb[(384 + j) * 3 + 1]);
            c1 = f1 * c1 + i1 * g1;
            float h1v = o1 * tanhfast(c1);

            h_s[j] = h0v;
            h_s[128 + j] = h1v;
            if (seq_out) {
                seq_out[((size_t)t * BB + b0 + 0) * 256 + dir * HH + j] = h0v;
                seq_out[((size_t)t * BB + b0 + 1) * 256 + dir * HH + j] = h1v;
            }
        }
        __syncthreads();
    }

    if (final_out && col < HH) {
        final_out[((size_t)dir * BB + b0 + 0) * HH + col] = h_s[col];
        final_out[((size_t)dir * BB + b0 + 1) * HH + col] = h_s[128 + col];
    }
}

// ---------------- final FC: out[b][c] = [hf|hb] . fc_w[c] + fc_b[c] ----------------
__global__ void k_fc(const float* __restrict__ fw, const float* __restrict__ fb,
                     float* __restrict__ out) {
    int tid = threadIdx.x;
    if (tid >= 256) return;
    int b = tid >> 1, cc = tid & 1;
    float acc = fb[cc];
#pragma unroll 4
    for (int k = 0; k < HH; k++) acc += g_hf[(size_t)0 * BB * HH + b * HH + k] * fw[cc * 256 + k];
#pragma unroll 4
    for (int k = 0; k < HH; k++) acc += g_hf[(size_t)1 * BB * HH + b * HH + k] * fw[cc * 256 + 128 + k];
    out[b * 2 + cc] = acc;
}

// ---------------- launch ----------------
extern "C" void kernel_launch(void* const* d_in, const int* in_sizes, int n_in,
                              void* d_out, int out_size) {
    const int* x = (const int*)d_in[0];
    const float* emb = (const float*)d_in[1];
    // [layer][dir]
    const float* w_ih[2][2] = {{(const float*)d_in[2],  (const float*)d_in[6]},
                               {(const float*)d_in[10], (const float*)d_in[14]}};
    const float* w_hh[2][2] = {{(const float*)d_in[3],  (const float*)d_in[7]},
                               {(const float*)d_in[11], (const float*)d_in[15]}};
    const float* b_ih[2][2] = {{(const float*)d_in[4],  (const float*)d_in[8]},
                               {(const float*)d_in[12], (const float*)d_in[16]}};
    const float* b_hh[2][2] = {{(const float*)d_in[5],  (const float*)d_in[9]},
                               {(const float*)d_in[13], (const float*)d_in[17]}};
    const float* fw = (const float*)d_in[18];
    const float* fb = (const float*)d_in[19];
    float* out = (float*)d_out;

    // unconditional every call: deterministic, idempotent, capture-legal
    cudaFuncSetAttribute(k_scan, cudaFuncAttributeMaxDynamicSharedMemorySize, SCAN_SMEM);

    float *p_e, *p_xp, *p_h0, *p_wt0, *p_wt1, *p_bs, *p_hf;
    __half* p_wch;
    cudaGetSymbolAddress((void**)&p_e, g_e);
    cudaGetSymbolAddress((void**)&p_xp, g_xp);
    cudaGetSymbolAddress((void**)&p_h0, g_h0);
    cudaGetSymbolAddress((void**)&p_wt0, g_wt0);
    cudaGetSymbolAddress((void**)&p_wt1, g_wt1);
    cudaGetSymbolAddress((void**)&p_wch, g_wch);
    cudaGetSymbolAddress((void**)&p_bs, g_bs);
    cudaGetSymbolAddress((void**)&p_hf, g_hf);

    // embedding (padded)
    k_embed<<<(int)(((size_t)MR * EPAD + 255) / 256), 256>>>(x, emb);

    // weight prep (z = direction)
    {
        dim3 g0((EPAD * NG + 255) / 256, 1, 2);
        k_wt<<<g0, 256>>>(w_ih[0][0], w_ih[0][1], p_wt0, 100, EPAD);
        dim3 g1((256 * NG + 255) / 256, 1, 2);
        k_wt<<<g1, 256>>>(w_ih[1][0], w_ih[1][1], p_wt1, 256, 256);
        dim3 gc((32 * NG * 4) / 256, 1, 2);
        k_wch<<<gc, 256>>>(w_hh[0][0], w_hh[0][1], p_wch);
        k_wch<<<gc, 256>>>(w_hh[1][0], w_hh[1][1], p_wch + (size_t)2 * 32 * NG * 4);
        k_bias<<<2, 256>>>(b_ih[0][0], b_hh[0][0], b_ih[0][1], b_hh[0][1], p_bs);
        k_bias<<<2, 256>>>(b_ih[1][0], b_hh[1][0], b_ih[1][1], b_hh[1][1], p_bs + 2 * NG);
    }

    // layer0 projection (both dirs in z) then scan
    dim3 gg(MR / 128, 4, 2);
    k_gemm<<<gg, 256>>>(p_e, p_wt0, p_bs, p_xp, MR, EPAD);
    k_scan<<<128, 512, SCAN_SMEM>>>(p_xp, p_wch, p_h0, nullptr);

    // layer1 projection (reuses xp buffer) then scan (final hidden only)
    k_gemm<<<gg, 256>>>(p_h0, p_wt1, p_bs + 2 * NG, p_xp, MR, 256);
    k_scan<<<128, 512, SCAN_SMEM>>>(p_xp, p_wch + (size_t)2 * 32 * NG * 4, nullptr, p_hf);

    // classifier head
    k_fc<<<1, 256>>>(fw, fb, out);
}

// round 17
// speedup vs baseline: 1.0948x; 1.0948x over previous
#include <cuda_runtime.h>
#include <cuda_fp16.h>
#include <cstdint>

#define BB 128
#define TT 1024
#define HH 128
#define NG 512
#define EPAD 112
#define MR (TT*BB)   // 131072

// ---------------- scratch (static device globals; no allocs) ----------------
__device__ float g_e[(size_t)MR * EPAD];        // embedded input, K padded to 112
__device__ float g_xp[(size_t)2 * MR * NG];     // gate pre-activations, reused per layer
__device__ float g_h0[(size_t)MR * 256];        // layer0 output [t][b][2H]
__device__ float g_wt0[2 * EPAD * NG];          // w_ih_l0^T padded, per dir
__device__ float g_wt1[2 * 256 * NG];           // w_ih_l1^T, per dir
__device__ __half g_wch[2 * 2 * 32 * NG * 4];   // w_hh fp16 [layer][dir][kc][col][4k]
__device__ float g_hf[2 * BB * HH];             // final hidden of layer1 [dir][b][j]

__device__ __forceinline__ float sigf(float x) { return 1.0f / (1.0f + __expf(-x)); }
__device__ __forceinline__ float tanhfast(float x) { return 2.0f / (1.0f + __expf(-2.0f * x)) - 1.0f; }

// packed f32x2 helpers (sm_103a FFMA2 path; see B300_MICROARCH / ptx_helpers)
#define FMA_F32X2(d, a, b, c) \
    asm("fma.rn.f32x2 %0, %1, %2, %3;" : "=l"(d) : "l"(a), "l"(b), "l"(c))
#define PACK2(d, lo, hi) \
    asm("mov.b64 %0, {%1, %2};" : "=l"(d) : "r"(__float_as_uint(lo)), "r"(__float_as_uint(hi)))
#define UNPACK2(lo, hi, s) \
    do { unsigned int _ulo, _uhi; \
         asm("mov.b64 {%0, %1}, %2;" : "=r"(_ulo), "=r"(_uhi) : "l"(s)); \
         lo = __uint_as_float(_ulo); hi = __uint_as_float(_uhi); } while (0)

// ---------------- embedding gather into padded [t][b][112] ----------------
__global__ void k_embed(const int* __restrict__ x, const float* __restrict__ emb) {
    size_t idx = (size_t)blockIdx.x * blockDim.x + threadIdx.x;
    if (idx >= (size_t)MR * EPAD) return;
    int d = (int)(idx % EPAD);
    size_t m = idx / EPAD;
    int b = (int)(m % BB);
    int t = (int)(m / BB);
    float v = 0.0f;
    if (d < 100) {
        int tok = x[b * TT + t];
        v = emb[(size_t)tok * 100 + d];
    }
    g_e[idx] = v;
}

// ---------------- weight prep ----------------
// wt[k][n] = w_ih[n][k], zero-padded in k (z = direction)
__global__ void k_wt(const float* __restrict__ w0, const float* __restrict__ w1,
                     float* __restrict__ wt, int K, int Kpad) {
    int idx = blockIdx.x * blockDim.x + threadIdx.x;
    if (idx >= Kpad * NG) return;
    const float* w = blockIdx.z ? w1 : w0;
    int n = idx % NG;
    int k = idx / NG;
    wt[(size_t)blockIdx.z * Kpad * NG + idx] = (k < K) ? w[n * K + k] : 0.0f;
}

// wch[(kc*512 + col)*4 + i] = fp16(w_hh[col][kc*4+i]); z = layer*2 + dir (4 slices)
__global__ void k_wch(const float* __restrict__ whA, const float* __restrict__ whB,
                      const float* __restrict__ whC, const float* __restrict__ whD,
                      __half* __restrict__ wc) {
    int idx = blockIdx.x * blockDim.x + threadIdx.x;
    if (idx >= 32 * NG * 4) return;
    int z = blockIdx.z;
    const float* whh = (z == 0) ? whA : (z == 1) ? whB : (z == 2) ? whC : whD;
    int i = idx & 3;
    int col = (idx >> 2) & (NG - 1);
    int kc = idx >> 11;
    wc[(size_t)z * 32 * NG * 4 + idx] = __float2half(whh[col * HH + kc * 4 + i]);
}

// ---------------- fp32 GEMM: C[M,512] = A[M,K] @ Bm[K,512] + (bi+bh) ----------
// BM=128, BN=128, BK=16, 256 threads, 8x8 microtile computed as 8x4 f32x2 lanes
// (FFMA2: halves fma-pipe occupancy vs scalar FFMA). Register double buffering.
// gridDim.z = direction: selects Bm/bias/C slice (A shared between dirs).
__global__ __launch_bounds__(256) void k_gemm(const float* __restrict__ A,
                                              const float* __restrict__ Bm_all,
                                              const float* __restrict__ bi0,
                                              const float* __restrict__ bh0,
                                              const float* __restrict__ bi1,
                                              const float* __restrict__ bh1,
                                              float* __restrict__ Cm_all,
                                              int M, int K) {
    const float* Bm = Bm_all + (size_t)blockIdx.z * K * NG;
    const float* bi = blockIdx.z ? bi1 : bi0;
    const float* bh = blockIdx.z ? bh1 : bh0;
    float* Cm = Cm_all + (size_t)blockIdx.z * MR * NG;

    __shared__ float As[16][128];
    __shared__ float Bs[16][128];
    int tid = threadIdx.x;
    int tx = tid & 15, ty = tid >> 4;
    int m0 = blockIdx.x * 128;
    int n0 = blockIdx.y * 128;

    unsigned long long acc2[8][4];   // [i][j2]: lo = col 2*j2, hi = col 2*j2+1
#pragma unroll
    for (int i = 0; i < 8; i++)
#pragma unroll
        for (int j = 0; j < 4; j++) acc2[i][j] = 0ull;

    int aRow[2], aKq[2], bRow[2], bC4[2];
#pragma unroll
    for (int q = 0; q < 2; q++) {
        int s = tid + q * 256;
        aRow[q] = s >> 2; aKq[q] = (s & 3) << 2;
        bRow[q] = s >> 5; bC4[q] = (s & 31) << 2;
    }

    float4 va[2], vb[2];
#pragma unroll
    for (int q = 0; q < 2; q++) {
        va[q] = *(const float4*)(A + (size_t)(m0 + aRow[q]) * K + aKq[q]);
        vb[q] = *(const float4*)(Bm + (size_t)bRow[q] * NG + n0 + bC4[q]);
    }

    for (int k0 = 0; k0 < K; k0 += 16) {
#pragma unroll
        for (int q = 0; q < 2; q++) {
            As[aKq[q] + 0][aRow[q]] = va[q].x;
            As[aKq[q] + 1][aRow[q]] = va[q].y;
            As[aKq[q] + 2][aRow[q]] = va[q].z;
            As[aKq[q] + 3][aRow[q]] = va[q].w;
            *(float4*)(&Bs[bRow[q]][bC4[q]]) = vb[q];
        }
        __syncthreads();
        int kn = k0 + 16;
        if (kn < K) {
#pragma unroll
            for (int q = 0; q < 2; q++) {
                va[q] = *(const float4*)(A + (size_t)(m0 + aRow[q]) * K + kn + aKq[q]);
                vb[q] = *(const float4*)(Bm + (size_t)(kn + bRow[q]) * NG + n0 + bC4[q]);
            }
        }
#pragma unroll
        for (int k = 0; k < 16; k++) {
            float ra[8], rb[8];
#pragma unroll
            for (int i = 0; i < 8; i++) ra[i] = As[k][ty * 8 + i];
#pragma unroll
            for (int j = 0; j < 8; j++) rb[j] = Bs[k][tx * 8 + j];
            unsigned long long b2[4];
#pragma unroll
            for (int j = 0; j < 4; j++) PACK2(b2[j], rb[2 * j], rb[2 * j + 1]);
#pragma unroll
            for (int i = 0; i < 8; i++) {
                unsigned long long a2;
                PACK2(a2, ra[i], ra[i]);
#pragma unroll
                for (int j = 0; j < 4; j++)
                    FMA_F32X2(acc2[i][j], a2, b2[j], acc2[i][j]);
            }
        }
        __syncthreads();
    }

    float bv[8];
#pragma unroll
    for (int j = 0; j < 8; j++) {
        int n = n0 + tx * 8 + j;
        bv[j] = bi[n] + bh[n];
    }
#pragma unroll
    for (int i = 0; i < 8; i++) {
        int m = m0 + ty * 8 + i;
        float c[8];
#pragma unroll
        for (int j = 0; j < 4; j++) UNPACK2(c[2 * j], c[2 * j + 1], acc2[i][j]);
        float4 o0, o1;
        o0.x = c[0] + bv[0]; o0.y = c[1] + bv[1];
        o0.z = c[2] + bv[2]; o0.w = c[3] + bv[3];
        o1.x = c[4] + bv[4]; o1.y = c[5] + bv[5];
        o1.z = c[6] + bv[6]; o1.w = c[7] + bv[7];
        *(float4*)(Cm + (size_t)m * NG + n0 + tx * 8) = o0;
        *(float4*)(Cm + (size_t)m * NG + n0 + tx * 8 + 4) = o1;
    }
}

// ---------------- recurrent scan (fp16 weights resident in dynamic smem) ----
// grid = 128: dir = bx>>6, batch-tile of 2 rows = bx&63. 512 threads = 1 gate col each.
// Gate phase split across 256 threads: thread col<256 owns (row=col>>7, j=col&127),
// 4 expf each (was 8 on 128 threads). c-state thread-private.
// Dynamic smem layout:
//   [0      .. 1024)   float h_s[2][128]
//   [1024   .. 7168)   float gb[512*3]   (stride-3 pad: conflict-free)
//   [7168   .. 138240) uint2 w2[32][512] (fp16 w_hh: [kc][col] -> 4 k-values)
#define SCAN_SMEM 138240
__global__ __launch_bounds__(512, 1) void k_scan(const float* __restrict__ xp_all,
                                                 const __half* __restrict__ wch_all,
                                                 float* __restrict__ seq_out,
                                                 float* __restrict__ final_out) {
    extern __shared__ __align__(16) char smem[];
    float* h_s = (float*)smem;                       // [2][128]
    float* gb = (float*)(smem + 1024);               // [512*3]
    uint2* w2 = (uint2*)(smem + 7168);               // [32*512]

    int dir = blockIdx.x >> 6;
    int tile = blockIdx.x & 63;
    int b0 = tile * 2;
    const float* xp = xp_all + (size_t)dir * MR * NG;
    const __half* wch = wch_all + (size_t)dir * (32 * NG * 4);

    int col = threadIdx.x;
    int grow = col >> 7;          // gate-phase batch row (threads 0..255)
    int gj = col & 127;           // gate-phase h column

    // preload fp16 weights into smem (128 KB), uint4 = 8 halves per load
    {
        const uint4* src = (const uint4*)wch;
        uint4* dst = (uint4*)w2;
#pragma unroll
        for (int i = 0; i < 16; i++) dst[col + (i << 9)] = src[col + (i << 9)];
    }
    if (col < 256) h_s[col] = 0.0f;
    float creg = 0.0f;            // cell state for (grow, gj), threads 0..255
    __syncthreads();

    for (int s = 0; s < TT; s++) {
        int t = dir ? (TT - 1 - s) : s;
        size_t base = ((size_t)t * BB + b0) * NG + col;
        float x0 = xp[base];
        float x1 = xp[base + NG];
        float s0 = 0.0f, s1 = 0.0f;
#pragma unroll
        for (int kc = 0; kc < 32; kc++) {
            uint2 wv = w2[(kc << 9) + col];
            float2 f01 = __half22float2(*(const __half2*)&wv.x);
            float2 f23 = __half22float2(*(const __half2*)&wv.y);
            float4 ha = *(const float4*)&h_s[kc << 2];
            float4 hb = *(const float4*)&h_s[128 + (kc << 2)];
            s0 += f01.x * ha.x; s0 += f01.y * ha.y; s0 += f23.x * ha.z; s0 += f23.y * ha.w;
            s1 += f01.x * hb.x; s1 += f01.y * hb.y; s1 += f23.x * hb.z; s1 += f23.y * hb.w;
        }
        gb[col * 3 + 0] = x0 + s0;
        gb[col * 3 + 1] = x1 + s1;
        __syncthreads();

        if (col < 256) {
            float iv = sigf(gb[gj * 3 + grow]);
            float fv = sigf(gb[(128 + gj) * 3 + grow]);
            float gv = tanhfast(gb[(256 + gj) * 3 + grow]);
            float ov = sigf(gb[(384 + gj) * 3 + grow]);
            creg = fv * creg + iv * gv;
            float hv = ov * tanhfast(creg);
            h_s[grow * 128 + gj] = hv;
            if (seq_out)
                seq_out[((size_t)t * BB + b0 + grow) * 256 + dir * HH + gj] = hv;
        }
        __syncthreads();
    }

    if (final_out && col < 256) {
        final_out[((size_t)dir * BB + b0 + grow) * HH + gj] = h_s[grow * 128 + gj];
    }
}

// ---------------- final FC: out[b][c] = [hf|hb] . fc_w[c] + fc_b[c] ----------------
__global__ void k_fc(const float* __restrict__ fw, const float* __restrict__ fb,
                     float* __restrict__ out) {
    int tid = threadIdx.x;
    if (tid >= 256) return;
    int b = tid >> 1, cc = tid & 1;
    float acc = fb[cc];
#pragma unroll 4
    for (int k = 0; k < HH; k++) acc += g_hf[(size_t)0 * BB * HH + b * HH + k] * fw[cc * 256 + k];
#pragma unroll 4
    for (int k = 0; k < HH; k++) acc += g_hf[(size_t)1 * BB * HH + b * HH + k] * fw[cc * 256 + 128 + k];
    out[b * 2 + cc] = acc;
}

// ---------------- launch ----------------
// Launch order matters: ncu capture lands on launch slot 5 = k_gemm(layer0).
extern "C" void kernel_launch(void* const* d_in, const int* in_sizes, int n_in,
                              void* d_out, int out_size) {
    const int* x = (const int*)d_in[0];
    const float* emb = (const float*)d_in[1];
    // [layer][dir]
    const float* w_ih[2][2] = {{(const float*)d_in[2],  (const float*)d_in[6]},
                               {(const float*)d_in[10], (const float*)d_in[14]}};
    const float* w_hh[2][2] = {{(const float*)d_in[3],  (const float*)d_in[7]},
                               {(const float*)d_in[11], (const float*)d_in[15]}};
    const float* b_ih[2][2] = {{(const float*)d_in[4],  (const float*)d_in[8]},
                               {(const float*)d_in[12], (const float*)d_in[16]}};
    const float* b_hh[2][2] = {{(const float*)d_in[5],  (const float*)d_in[9]},
                               {(const float*)d_in[13], (const float*)d_in[17]}};
    const float* fw = (const float*)d_in[18];
    const float* fb = (const float*)d_in[19];
    float* out = (float*)d_out;

    // unconditional every call: deterministic, idempotent, capture-legal
    cudaFuncSetAttribute(k_scan, cudaFuncAttributeMaxDynamicSharedMemorySize, SCAN_SMEM);

    float *p_e, *p_xp, *p_h0, *p_wt0, *p_wt1, *p_hf;
    __half* p_wch;
    cudaGetSymbolAddress((void**)&p_e, g_e);
    cudaGetSymbolAddress((void**)&p_xp, g_xp);
    cudaGetSymbolAddress((void**)&p_h0, g_h0);
    cudaGetSymbolAddress((void**)&p_wt0, g_wt0);
    cudaGetSymbolAddress((void**)&p_wt1, g_wt1);
    cudaGetSymbolAddress((void**)&p_wch, g_wch);
    cudaGetSymbolAddress((void**)&p_hf, g_hf);

    // 1: embedding (padded)
    k_embed<<<(int)(((size_t)MR * EPAD + 255) / 256), 256>>>(x, emb);

    // 2-3: input-projection weight transposes (z = direction)
    dim3 g0((EPAD * NG + 255) / 256, 1, 2);
    k_wt<<<g0, 256>>>(w_ih[0][0], w_ih[0][1], p_wt0, 100, EPAD);
    dim3 g1((256 * NG + 255) / 256, 1, 2);
    k_wt<<<g1, 256>>>(w_ih[1][0], w_ih[1][1], p_wt1, 256, 256);

    // 4: recurrent weights fp16, all 4 (layer,dir) slices in one launch
    dim3 gc((32 * NG * 4) / 256, 1, 4);
    k_wch<<<gc, 256>>>(w_hh[0][0], w_hh[0][1], w_hh[1][0], w_hh[1][1], p_wch);

    // 5: layer0 projection (both dirs in z) — ncu capture slot
    dim3 gg(MR / 128, 4, 2);
    k_gemm<<<gg, 256>>>(p_e, p_wt0, b_ih[0][0], b_hh[0][0], b_ih[0][1], b_hh[0][1],
                        p_xp, MR, EPAD);
    // 6: layer0 scan
    k_scan<<<128, 512, SCAN_SMEM>>>(p_xp, p_wch, p_h0, nullptr);

    // 7: layer1 projection (reuses xp buffer)
    k_gemm<<<gg, 256>>>(p_h0, p_wt1, b_ih[1][0], b_hh[1][0], b_ih[1][1], b_hh[1][1],
                        p_xp, MR, 256);
    // 8: layer1 scan (final hidden only)
    k_scan<<<128, 512, SCAN_SMEM>>>(p_xp, p_wch + (size_t)2 * 32 * NG * 4, nullptr, p_hf);

    // 9: classifier head
    k_fc<<<1, 256>>>(fw, fb, out);
}